// round 4
// baseline (speedup 1.0000x reference)
#include <cuda_runtime.h>
#include <cuda_bf16.h>
#include <cstdint>
#include <cstddef>

// Problem constants (fixed-shape problem)
#define NN 100000
#define NE 600000
#define NB 512
#define HD 128
#define EDF 8

// ---------------- device scratch (static allocation is the sanctioned path) ---
__device__ float g_x0[NN];                 // id feature
__device__ float g_x[NN * HD];             // node features
__device__ float g_h[NN * HD];             // x + aggr (scatter target)
__device__ float g_e[(size_t)NE * HD];     // edge embeddings (307 MB)
__device__ float g_pool[NB * HD];
__device__ int   g_cnt[NB];

// ---------------- packed fp32x2 helpers --------------------------------------
__device__ __forceinline__ unsigned long long pack2(float x, float y) {
    unsigned long long r;
    asm("mov.b64 %0, {%1, %2};" : "=l"(r) : "f"(x), "f"(y));
    return r;
}
__device__ __forceinline__ void unpack2(unsigned long long v, float& x, float& y) {
    asm("mov.b64 {%0, %1}, %2;" : "=f"(x), "=f"(y) : "l"(v));
}
__device__ __forceinline__ void fma2(unsigned long long& c, unsigned long long a,
                                     unsigned long long b) {
    asm("fma.rn.f32x2 %0, %1, %2, %0;" : "+l"(c) : "l"(a), "l"(b));
}

// ---------------- x0 = clip(id / (2^48-1), 0, 1) -----------------------------
__global__ void x0_kernel(const int* __restrict__ ids, float* __restrict__ x0, int n) {
    int i = blockIdx.x * blockDim.x + threadIdx.x;
    if (i < n) {
        const float inv = 1.0f / 281474976710655.0f;  // 2^48 - 1
        float v = (float)ids[i] * inv;
        x0[i] = fminf(fmaxf(v, 0.0f), 1.0f);
    }
}

// ---------------- fused 2-layer MLP: Y = act(relu(X@W1+b1)@W2+b2) ------------
// Tile: 128 rows x 128 cols per CTA, 256 threads, packed f32x2 FMAs.
// Thread (tr, tc): tr = tid/16 -> rows tr*8..+7 ; tc = tid%16 -> col pairs
// {tc*2 + 32*m | m=0..3} (strided so warp B-loads are conflict-free).
template <int DIN, bool RELU_OUT>
__global__ void __launch_bounds__(256, 1)
mlp2_kernel(const float* __restrict__ X, int M,
            const float* __restrict__ W1, const float* __restrict__ B1,
            const float* __restrict__ W2, const float* __restrict__ B2,
            float* __restrict__ Y) {
    constexpr int TM = 128;
    constexpr int LDA = (DIN == 1) ? 2 : ((DIN & 3) ? DIN : DIN + 2);  // row pad: 8*LDA % 32 == 16
    constexpr int LDH = 130;

    extern __shared__ float sm[];
    float* sW = sm;                 // 128*128 floats (reused: W1 then W2)
    float* sA = sW + HD * HD;       // TM * LDA
    float* sH = sA + TM * LDA;      // TM * LDH

    const int tid = threadIdx.x;
    const int tr = tid >> 4;        // 0..15
    const int tc = tid & 15;        // 0..15
    const int r0 = tr * 8;
    const int m0 = blockIdx.x * TM;
    const int rows = min(TM, M - m0);

    // load W1
    for (int i = tid; i < DIN * HD; i += 256) sW[i] = W1[i];
    // load X tile (zero-pad tail rows)
    for (int i = tid; i < TM * DIN; i += 256) {
        int r = i / DIN, k = i - r * DIN;
        sA[r * LDA + k] = (r < rows) ? X[(size_t)(m0 + r) * DIN + k] : 0.0f;
    }
    __syncthreads();

    // ---- stage 1: sH = relu(sA @ W1 + b1) ----
    {
        unsigned long long acc[8][4];
#pragma unroll
        for (int i = 0; i < 8; i++)
#pragma unroll
            for (int m = 0; m < 4; m++) acc[i][m] = 0ull;

#pragma unroll 4
        for (int k = 0; k < DIN; k++) {
            unsigned long long b[4];
#pragma unroll
            for (int m = 0; m < 4; m++)
                b[m] = *(const unsigned long long*)&sW[k * HD + tc * 2 + 32 * m];
#pragma unroll
            for (int i = 0; i < 8; i++) {
                float a = sA[(r0 + i) * LDA + k];
                unsigned long long a2 = pack2(a, a);
#pragma unroll
                for (int m = 0; m < 4; m++) fma2(acc[i][m], a2, b[m]);
            }
        }
#pragma unroll
        for (int m = 0; m < 4; m++) {
            float bx = B1[tc * 2 + 32 * m];
            float by = B1[tc * 2 + 32 * m + 1];
#pragma unroll
            for (int i = 0; i < 8; i++) {
                float x, y;
                unpack2(acc[i][m], x, y);
                x = fmaxf(x + bx, 0.0f);
                y = fmaxf(y + by, 0.0f);
                float2 v = make_float2(x, y);
                *(float2*)&sH[(r0 + i) * LDH + tc * 2 + 32 * m] = v;
            }
        }
    }
    __syncthreads();
    // load W2 over W1's space
    for (int i = tid; i < HD * HD; i += 256) sW[i] = W2[i];
    __syncthreads();

    // ---- stage 2: Y = act(sH @ W2 + b2) ----
    {
        unsigned long long acc[8][4];
#pragma unroll
        for (int i = 0; i < 8; i++)
#pragma unroll
            for (int m = 0; m < 4; m++) acc[i][m] = 0ull;

#pragma unroll 4
        for (int k = 0; k < HD; k++) {
            unsigned long long b[4];
#pragma unroll
            for (int m = 0; m < 4; m++)
                b[m] = *(const unsigned long long*)&sW[k * HD + tc * 2 + 32 * m];
#pragma unroll
            for (int i = 0; i < 8; i++) {
                float a = sH[(r0 + i) * LDH + k];
                unsigned long long a2 = pack2(a, a);
#pragma unroll
                for (int m = 0; m < 4; m++) fma2(acc[i][m], a2, b[m]);
            }
        }
#pragma unroll
        for (int m = 0; m < 4; m++) {
            float bx = B2[tc * 2 + 32 * m];
            float by = B2[tc * 2 + 32 * m + 1];
#pragma unroll
            for (int i = 0; i < 8; i++) {
                if (r0 + i < rows) {
                    float x, y;
                    unpack2(acc[i][m], x, y);
                    x += bx; y += by;
                    if (RELU_OUT) { x = fmaxf(x, 0.0f); y = fmaxf(y, 0.0f); }
                    float2 v = make_float2(x, y);
                    *(float2*)&Y[(size_t)(m0 + r0 + i) * HD + tc * 2 + 32 * m] = v;
                }
            }
        }
    }
}

// ---------------- copy kernel (aggr init = x) --------------------------------
__global__ void copy_kernel(float4* __restrict__ dst, const float4* __restrict__ src, int n4) {
    int i = blockIdx.x * blockDim.x + threadIdx.x;
    if (i < n4) dst[i] = src[i];
}

// ---------------- scatter: aggr[dst] += relu(x[src] + e) ---------------------
// warp per edge: 32 threads x 4 floats = 128 cols; x/e row reads fully coalesced
__global__ void scatter_kernel(const float* __restrict__ x, const float* __restrict__ e,
                               const int* __restrict__ src, const int* __restrict__ dst,
                               float* __restrict__ aggr, int nE) {
    long long idx = (long long)blockIdx.x * blockDim.x + threadIdx.x;
    int eidx = (int)(idx >> 5);
    if (eidx >= nE) return;
    int c4 = ((int)idx & 31) * 4;
    int s = src[eidx];
    int d = dst[eidx];
    float4 xv = *(const float4*)&x[(size_t)s * HD + c4];
    float4 ev = *(const float4*)&e[(size_t)eidx * HD + c4];
    float* ap = &aggr[(size_t)d * HD + c4];
    atomicAdd(ap + 0, fmaxf(xv.x + ev.x, 0.0f));
    atomicAdd(ap + 1, fmaxf(xv.y + ev.y, 0.0f));
    atomicAdd(ap + 2, fmaxf(xv.z + ev.z, 0.0f));
    atomicAdd(ap + 3, fmaxf(xv.w + ev.w, 0.0f));
}

// ---------------- pooling ----------------------------------------------------
__global__ void zero_pool_kernel(float* __restrict__ pool, int* __restrict__ cnt) {
    int i = blockIdx.x * blockDim.x + threadIdx.x;
    if (i < NB * HD) pool[i] = 0.0f;
    if (i < NB) cnt[i] = 0;
}

__global__ void pool_kernel(const float* __restrict__ x, const int* __restrict__ batch,
                            float* __restrict__ pool, int* __restrict__ cnt, int n) {
    long long idx = (long long)blockIdx.x * blockDim.x + threadIdx.x;
    int node = (int)(idx >> 5);
    if (node >= n) return;
    int c4 = ((int)idx & 31) * 4;
    int b = batch[node];
    float4 v = *(const float4*)&x[(size_t)node * HD + c4];
    float* pp = &pool[(size_t)b * HD + c4];
    atomicAdd(pp + 0, v.x);
    atomicAdd(pp + 1, v.y);
    atomicAdd(pp + 2, v.z);
    atomicAdd(pp + 3, v.w);
    if (c4 == 0) atomicAdd(&cnt[b], 1);
}

// ---------------- regressor: out[b] = mlp2([mean_b, depth_b]) ----------------
__global__ void regressor_kernel(const float* __restrict__ pool, const int* __restrict__ cnt,
                                 const float* __restrict__ depth,
                                 const float* __restrict__ w1, const float* __restrict__ b1,
                                 const float* __restrict__ w2, const float* __restrict__ b2,
                                 float* __restrict__ out) {
    int b = blockIdx.x;
    int j = threadIdx.x;  // 0..127
    __shared__ float mean[HD];
    __shared__ float red[HD];
    float c = fmaxf((float)cnt[b], 1.0f);
    mean[j] = pool[(size_t)b * HD + j] / c;
    __syncthreads();
    float acc = b1[j];
#pragma unroll 4
    for (int k = 0; k < HD; k++) acc = fmaf(mean[k], w1[k * HD + j], acc);
    acc = fmaf(depth[b], w1[HD * HD + j], acc);
    red[j] = fmaxf(acc, 0.0f) * w2[j];
    __syncthreads();
    for (int s = 64; s > 0; s >>= 1) {
        if (j < s) red[j] += red[j + s];
        __syncthreads();
    }
    if (j == 0) out[b] = red[0] + b2[0];
}

// ---------------- launch -----------------------------------------------------
extern "C" void kernel_launch(void* const* d_in, const int* in_sizes, int n_in,
                              void* d_out, int out_size) {
    const int*   node_ids  = (const int*)d_in[0];
    const int*   edge_idx  = (const int*)d_in[1];   // [2, E]
    const float* edge_attr = (const float*)d_in[2]; // [E, 8]
    const int*   batch     = (const int*)d_in[3];
    const float* depth     = (const float*)d_in[4];
    const float* id_w1 = (const float*)d_in[5];
    const float* id_b1 = (const float*)d_in[6];
    const float* id_w2 = (const float*)d_in[7];
    const float* id_b2 = (const float*)d_in[8];
    const float* ed_w1 = (const float*)d_in[9];
    const float* ed_b1 = (const float*)d_in[10];
    const float* ed_w2 = (const float*)d_in[11];
    const float* ed_b2 = (const float*)d_in[12];
    const float* c1_w1 = (const float*)d_in[13];
    const float* c1_b1 = (const float*)d_in[14];
    const float* c1_w2 = (const float*)d_in[15];
    const float* c1_b2 = (const float*)d_in[16];
    const float* c2_w1 = (const float*)d_in[17];
    const float* c2_b1 = (const float*)d_in[18];
    const float* c2_w2 = (const float*)d_in[19];
    const float* c2_b2 = (const float*)d_in[20];
    const float* rg_w1 = (const float*)d_in[21];
    const float* rg_b1 = (const float*)d_in[22];
    const float* rg_w2 = (const float*)d_in[23];
    const float* rg_b2 = (const float*)d_in[24];
    float* out = (float*)d_out;

    const int* src = edge_idx;
    const int* dst = edge_idx + NE;

    // scratch symbol addresses
    float *x0p, *xp, *hp, *ep, *poolp;
    int* cntp;
    cudaGetSymbolAddress((void**)&x0p, g_x0);
    cudaGetSymbolAddress((void**)&xp, g_x);
    cudaGetSymbolAddress((void**)&hp, g_h);
    cudaGetSymbolAddress((void**)&ep, g_e);
    cudaGetSymbolAddress((void**)&poolp, g_pool);
    cudaGetSymbolAddress((void**)&cntp, g_cnt);

    // dynamic smem sizes
    const int smem1   = (HD * HD + 128 * 2   + 128 * 130) * 4;
    const int smem8   = (HD * HD + 128 * 10  + 128 * 130) * 4;
    const int smem128 = (HD * HD + 128 * 130 + 128 * 130) * 4;
    cudaFuncSetAttribute(mlp2_kernel<1, false>,  cudaFuncAttributeMaxDynamicSharedMemorySize, smem1);
    cudaFuncSetAttribute(mlp2_kernel<8, false>,  cudaFuncAttributeMaxDynamicSharedMemorySize, smem8);
    cudaFuncSetAttribute(mlp2_kernel<128, true>, cudaFuncAttributeMaxDynamicSharedMemorySize, smem128);

    const int gridN128 = (NN + 127) / 128;
    const int gridE128 = (NE + 127) / 128;

    // 1) id features
    x0_kernel<<<(NN + 255) / 256, 256>>>(node_ids, x0p, NN);
    mlp2_kernel<1, false><<<gridN128, 256, smem1>>>(x0p, NN, id_w1, id_b1, id_w2, id_b2, xp);

    // 2) edge embeddings
    mlp2_kernel<8, false><<<gridE128, 256, smem8>>>(edge_attr, NE, ed_w1, ed_b1, ed_w2, ed_b2, ep);

    // 3) conv 1
    {
        int n4 = NN * HD / 4;
        copy_kernel<<<(n4 + 255) / 256, 256>>>((float4*)hp, (const float4*)xp, n4);
        long long t = (long long)NE * 32;
        scatter_kernel<<<(int)((t + 255) / 256), 256>>>(xp, ep, src, dst, hp, NE);
        mlp2_kernel<128, true><<<gridN128, 256, smem128>>>(hp, NN, c1_w1, c1_b1, c1_w2, c1_b2, xp);
    }
    // 4) conv 2
    {
        int n4 = NN * HD / 4;
        copy_kernel<<<(n4 + 255) / 256, 256>>>((float4*)hp, (const float4*)xp, n4);
        long long t = (long long)NE * 32;
        scatter_kernel<<<(int)((t + 255) / 256), 256>>>(xp, ep, src, dst, hp, NE);
        mlp2_kernel<128, true><<<gridN128, 256, smem128>>>(hp, NN, c2_w1, c2_b1, c2_w2, c2_b2, xp);
    }

    // 5) pool + regressor
    zero_pool_kernel<<<(NB * HD + 255) / 256, 256>>>(poolp, cntp);
    {
        long long t = (long long)NN * 32;
        pool_kernel<<<(int)((t + 255) / 256), 256>>>(xp, batch, poolp, cntp, NN);
    }
    regressor_kernel<<<NB, HD>>>(poolp, cntp, depth, rg_w1, rg_b1, rg_w2, rg_b2, out);
}

// round 6
// speedup vs baseline: 1.7350x; 1.7350x over previous
#include <cuda_runtime.h>
#include <cuda_bf16.h>
#include <cstdint>
#include <cstddef>

// Problem constants (fixed-shape problem)
#define NN 100000
#define NE 600000
#define NB 512
#define HD 128
#define EDF 8

// ---------------- device scratch (256B-aligned: float4 / red.v4 paths) -------
__device__ __align__(256) float g_x0[NN];                 // id feature
__device__ __align__(256) float g_x[NN * HD];             // node features
__device__ __align__(256) float g_h[NN * HD];             // aggr (scatter target)
__device__ __align__(256) float g_e[(size_t)NE * HD];     // edge embeddings (307 MB)
__device__ __align__(256) float g_pool[NB * HD];
__device__ __align__(256) int   g_cnt[NB];

// ---------------- packed fp32x2 helpers --------------------------------------
__device__ __forceinline__ unsigned long long pack2(float x, float y) {
    unsigned long long r;
    asm("mov.b64 %0, {%1, %2};" : "=l"(r) : "f"(x), "f"(y));
    return r;
}
__device__ __forceinline__ void unpack2(unsigned long long v, float& x, float& y) {
    asm("mov.b64 {%0, %1}, %2;" : "=f"(x), "=f"(y) : "l"(v));
}
__device__ __forceinline__ void fma2(unsigned long long& c, unsigned long long a,
                                     unsigned long long b) {
    asm("fma.rn.f32x2 %0, %1, %2, %0;" : "+l"(c) : "l"(a), "l"(b));
}
// vectorized atomic add (no return): 1 L2 transaction per 16B, 4x fewer atomic ops
__device__ __forceinline__ void red_add_v4(float* addr, float4 v) {
    asm volatile("red.global.add.v4.f32 [%0], {%1, %2, %3, %4};"
                 :: "l"(addr), "f"(v.x), "f"(v.y), "f"(v.z), "f"(v.w) : "memory");
}

// ---------------- x0 = clip(id / (2^48-1), 0, 1) -----------------------------
__global__ void x0_kernel(const int* __restrict__ ids, float* __restrict__ x0, int n) {
    int i = blockIdx.x * blockDim.x + threadIdx.x;
    if (i < n) {
        const float inv = 1.0f / 281474976710655.0f;  // 2^48 - 1
        float v = (float)ids[i] * inv;
        x0[i] = fminf(fmaxf(v, 0.0f), 1.0f);
    }
}

// ---------------- zero kernel ------------------------------------------------
__global__ void zero4_kernel(float4* __restrict__ p, int n4) {
    int i = blockIdx.x * blockDim.x + threadIdx.x;
    if (i < n4) p[i] = make_float4(0.f, 0.f, 0.f, 0.f);
}

// ---------------- fused 2-layer MLP: Y = act(relu((X[+X2])@W1+b1)@W2+b2) -----
// Tile: 128 rows x 128 cols per CTA, 256 threads, packed f32x2 FMAs.
// Thread (tr, tc): rows tr*8..+7, col pairs {tc*2 + 32*m | m=0..3}.
template <int DIN, bool RELU_OUT, bool ADD2>
__global__ void __launch_bounds__(256, 1)
mlp2_kernel(const float* __restrict__ X, const float* __restrict__ X2, int M,
            const float* __restrict__ W1, const float* __restrict__ B1,
            const float* __restrict__ W2, const float* __restrict__ B2,
            float* __restrict__ Y) {
    constexpr int TM = 128;
    constexpr int LDA = (DIN == 1) ? 2 : ((DIN & 3) ? DIN : DIN + 2);  // 8*LDA % 32 == 16
    constexpr int LDH = 130;

    extern __shared__ float sm[];
    float* sW = sm;                 // 128*128 floats (W1 then W2)
    float* sA = sW + HD * HD;       // TM * LDA
    float* sH = sA + TM * LDA;      // TM * LDH

    const int tid = threadIdx.x;
    const int tr = tid >> 4;        // 0..15
    const int tc = tid & 15;        // 0..15
    const int r0 = tr * 8;
    const int m0 = blockIdx.x * TM;
    const int rows = min(TM, M - m0);

    // load W1
    for (int i = tid; i < DIN * HD; i += 256) sW[i] = W1[i];
    // load X tile (zero-pad tail rows), vectorized when DIN % 4 == 0
    if (DIN == 1) {
        for (int i = tid; i < TM; i += 256)
            sA[i * LDA] = (i < rows) ? X[m0 + i] : 0.0f;
    } else {
        constexpr int D4 = DIN / 4;
        for (int i = tid; i < TM * D4; i += 256) {
            int r = i / D4, k4 = i - r * D4;
            float4 v = make_float4(0.f, 0.f, 0.f, 0.f);
            if (r < rows) {
                v = *(const float4*)&X[(size_t)(m0 + r) * DIN + k4 * 4];
                if (ADD2) {
                    float4 w = *(const float4*)&X2[(size_t)(m0 + r) * DIN + k4 * 4];
                    v.x += w.x; v.y += w.y; v.z += w.z; v.w += w.w;
                }
            }
            float* d = &sA[r * LDA + k4 * 4];
            d[0] = v.x; d[1] = v.y; d[2] = v.z; d[3] = v.w;
        }
    }
    __syncthreads();

    // ---- stage 1: sH = relu(sA @ W1 + b1) ----
    {
        unsigned long long acc[8][4];
#pragma unroll
        for (int i = 0; i < 8; i++)
#pragma unroll
            for (int m = 0; m < 4; m++) acc[i][m] = 0ull;

#pragma unroll 4
        for (int k = 0; k < DIN; k++) {
            unsigned long long b[4];
#pragma unroll
            for (int m = 0; m < 4; m++)
                b[m] = *(const unsigned long long*)&sW[k * HD + tc * 2 + 32 * m];
#pragma unroll
            for (int i = 0; i < 8; i++) {
                float a = sA[(r0 + i) * LDA + k];
                unsigned long long a2 = pack2(a, a);
#pragma unroll
                for (int m = 0; m < 4; m++) fma2(acc[i][m], a2, b[m]);
            }
        }
#pragma unroll
        for (int m = 0; m < 4; m++) {
            float bx = B1[tc * 2 + 32 * m];
            float by = B1[tc * 2 + 32 * m + 1];
#pragma unroll
            for (int i = 0; i < 8; i++) {
                float x, y;
                unpack2(acc[i][m], x, y);
                x = fmaxf(x + bx, 0.0f);
                y = fmaxf(y + by, 0.0f);
                *(float2*)&sH[(r0 + i) * LDH + tc * 2 + 32 * m] = make_float2(x, y);
            }
        }
    }
    __syncthreads();
    // load W2 over W1's space
    for (int i = tid; i < HD * HD; i += 256) sW[i] = W2[i];
    __syncthreads();

    // ---- stage 2: Y = act(sH @ W2 + b2) ----
    {
        unsigned long long acc[8][4];
#pragma unroll
        for (int i = 0; i < 8; i++)
#pragma unroll
            for (int m = 0; m < 4; m++) acc[i][m] = 0ull;

#pragma unroll 4
        for (int k = 0; k < HD; k++) {
            unsigned long long b[4];
#pragma unroll
            for (int m = 0; m < 4; m++)
                b[m] = *(const unsigned long long*)&sW[k * HD + tc * 2 + 32 * m];
#pragma unroll
            for (int i = 0; i < 8; i++) {
                float a = sH[(r0 + i) * LDH + k];
                unsigned long long a2 = pack2(a, a);
#pragma unroll
                for (int m = 0; m < 4; m++) fma2(acc[i][m], a2, b[m]);
            }
        }
#pragma unroll
        for (int m = 0; m < 4; m++) {
            float bx = B2[tc * 2 + 32 * m];
            float by = B2[tc * 2 + 32 * m + 1];
#pragma unroll
            for (int i = 0; i < 8; i++) {
                if (r0 + i < rows) {
                    float x, y;
                    unpack2(acc[i][m], x, y);
                    x += bx; y += by;
                    if (RELU_OUT) { x = fmaxf(x, 0.0f); y = fmaxf(y, 0.0f); }
                    *(float2*)&Y[(size_t)(m0 + r0 + i) * HD + tc * 2 + 32 * m] =
                        make_float2(x, y);
                }
            }
        }
    }
}

// ---------------- scatter: aggr[dst] += relu(x[src] + e) ---------------------
// warp per edge: 32 threads x 4 floats = 128 cols; vector RED atomics
__global__ void scatter_kernel(const float* __restrict__ x, const float* __restrict__ e,
                               const int* __restrict__ src, const int* __restrict__ dst,
                               float* __restrict__ aggr, int nE) {
    long long idx = (long long)blockIdx.x * blockDim.x + threadIdx.x;
    int eidx = (int)(idx >> 5);
    if (eidx >= nE) return;
    int c4 = ((int)idx & 31) * 4;
    int s = src[eidx];
    int d = dst[eidx];
    float4 xv = *(const float4*)&x[(size_t)s * HD + c4];
    float4 ev = *(const float4*)&e[(size_t)eidx * HD + c4];
    float4 m;
    m.x = fmaxf(xv.x + ev.x, 0.0f);
    m.y = fmaxf(xv.y + ev.y, 0.0f);
    m.z = fmaxf(xv.z + ev.z, 0.0f);
    m.w = fmaxf(xv.w + ev.w, 0.0f);
    red_add_v4(&aggr[(size_t)d * HD + c4], m);
}

// ---------------- pooling ----------------------------------------------------
__global__ void zero_pool_kernel(float* __restrict__ pool, int* __restrict__ cnt) {
    int i = blockIdx.x * blockDim.x + threadIdx.x;
    if (i < NB * HD) pool[i] = 0.0f;
    if (i < NB) cnt[i] = 0;
}

__global__ void pool_kernel(const float* __restrict__ x, const int* __restrict__ batch,
                            float* __restrict__ pool, int* __restrict__ cnt, int n) {
    long long idx = (long long)blockIdx.x * blockDim.x + threadIdx.x;
    int node = (int)(idx >> 5);
    if (node >= n) return;
    int c4 = ((int)idx & 31) * 4;
    int b = batch[node];
    float4 v = *(const float4*)&x[(size_t)node * HD + c4];
    red_add_v4(&pool[(size_t)b * HD + c4], v);
    if (c4 == 0) atomicAdd(&cnt[b], 1);
}

// ---------------- regressor: out[b] = mlp2([mean_b, depth_b]) ----------------
__global__ void regressor_kernel(const float* __restrict__ pool, const int* __restrict__ cnt,
                                 const float* __restrict__ depth,
                                 const float* __restrict__ w1, const float* __restrict__ b1,
                                 const float* __restrict__ w2, const float* __restrict__ b2,
                                 float* __restrict__ out) {
    int b = blockIdx.x;
    int j = threadIdx.x;  // 0..127
    __shared__ float mean[HD];
    __shared__ float red[HD];
    float c = fmaxf((float)cnt[b], 1.0f);
    mean[j] = pool[(size_t)b * HD + j] / c;
    __syncthreads();
    float acc = b1[j];
#pragma unroll 4
    for (int k = 0; k < HD; k++) acc = fmaf(mean[k], w1[k * HD + j], acc);
    acc = fmaf(depth[b], w1[HD * HD + j], acc);
    red[j] = fmaxf(acc, 0.0f) * w2[j];
    __syncthreads();
    for (int s = 64; s > 0; s >>= 1) {
        if (j < s) red[j] += red[j + s];
        __syncthreads();
    }
    if (j == 0) out[b] = red[0] + b2[0];
}

// ---------------- launch -----------------------------------------------------
extern "C" void kernel_launch(void* const* d_in, const int* in_sizes, int n_in,
                              void* d_out, int out_size) {
    const int*   node_ids  = (const int*)d_in[0];
    const int*   edge_idx  = (const int*)d_in[1];   // [2, E]
    const float* edge_attr = (const float*)d_in[2]; // [E, 8]
    const int*   batch     = (const int*)d_in[3];
    const float* depth     = (const float*)d_in[4];
    const float* id_w1 = (const float*)d_in[5];
    const float* id_b1 = (const float*)d_in[6];
    const float* id_w2 = (const float*)d_in[7];
    const float* id_b2 = (const float*)d_in[8];
    const float* ed_w1 = (const float*)d_in[9];
    const float* ed_b1 = (const float*)d_in[10];
    const float* ed_w2 = (const float*)d_in[11];
    const float* ed_b2 = (const float*)d_in[12];
    const float* c1_w1 = (const float*)d_in[13];
    const float* c1_b1 = (const float*)d_in[14];
    const float* c1_w2 = (const float*)d_in[15];
    const float* c1_b2 = (const float*)d_in[16];
    const float* c2_w1 = (const float*)d_in[17];
    const float* c2_b1 = (const float*)d_in[18];
    const float* c2_w2 = (const float*)d_in[19];
    const float* c2_b2 = (const float*)d_in[20];
    const float* rg_w1 = (const float*)d_in[21];
    const float* rg_b1 = (const float*)d_in[22];
    const float* rg_w2 = (const float*)d_in[23];
    const float* rg_b2 = (const float*)d_in[24];
    float* out = (float*)d_out;

    const int* src = edge_idx;
    const int* dst = edge_idx + NE;

    float *x0p, *xp, *hp, *ep, *poolp;
    int* cntp;
    cudaGetSymbolAddress((void**)&x0p, g_x0);
    cudaGetSymbolAddress((void**)&xp, g_x);
    cudaGetSymbolAddress((void**)&hp, g_h);
    cudaGetSymbolAddress((void**)&ep, g_e);
    cudaGetSymbolAddress((void**)&poolp, g_pool);
    cudaGetSymbolAddress((void**)&cntp, g_cnt);

    // dynamic smem: sW (128*128) + sA (128*LDA) + sH (128*130), LDA per DIN
    const int smem1   = (HD * HD + 128 * 2   + 128 * 130) * 4;
    const int smem8   = (HD * HD + 128 * 10  + 128 * 130) * 4;   // LDA(DIN=8)=10 !
    const int smem128 = (HD * HD + 128 * 130 + 128 * 130) * 4;
    cudaFuncSetAttribute(mlp2_kernel<1, false, false>,  cudaFuncAttributeMaxDynamicSharedMemorySize, smem1);
    cudaFuncSetAttribute(mlp2_kernel<8, false, false>,  cudaFuncAttributeMaxDynamicSharedMemorySize, smem8);
    cudaFuncSetAttribute(mlp2_kernel<128, true, true>,  cudaFuncAttributeMaxDynamicSharedMemorySize, smem128);

    const int gridN128 = (NN + 127) / 128;
    const int gridE128 = (NE + 127) / 128;
    const int nh4 = NN * HD / 4;

    // 1) id features
    x0_kernel<<<(NN + 255) / 256, 256>>>(node_ids, x0p, NN);
    zero4_kernel<<<(nh4 + 255) / 256, 256>>>((float4*)hp, nh4);
    mlp2_kernel<1, false, false><<<gridN128, 256, smem1>>>(
        x0p, nullptr, NN, id_w1, id_b1, id_w2, id_b2, xp);

    // 2) edge embeddings
    mlp2_kernel<8, false, false><<<gridE128, 256, smem8>>>(
        edge_attr, nullptr, NE, ed_w1, ed_b1, ed_w2, ed_b2, ep);

    // 3) conv 1: h = scatter(relu(x[src]+e)) ; x = relu(nn(x + h))
    {
        long long t = (long long)NE * 32;
        scatter_kernel<<<(int)((t + 255) / 256), 256>>>(xp, ep, src, dst, hp, NE);
        mlp2_kernel<128, true, true><<<gridN128, 256, smem128>>>(
            xp, hp, NN, c1_w1, c1_b1, c1_w2, c1_b2, xp);
    }
    // 4) conv 2
    {
        zero4_kernel<<<(nh4 + 255) / 256, 256>>>((float4*)hp, nh4);
        long long t = (long long)NE * 32;
        scatter_kernel<<<(int)((t + 255) / 256), 256>>>(xp, ep, src, dst, hp, NE);
        mlp2_kernel<128, true, true><<<gridN128, 256, smem128>>>(
            xp, hp, NN, c2_w1, c2_b1, c2_w2, c2_b2, xp);
    }

    // 5) pool + regressor
    zero_pool_kernel<<<(NB * HD + 255) / 256, 256>>>(poolp, cntp);
    {
        long long t = (long long)NN * 32;
        pool_kernel<<<(int)((t + 255) / 256), 256>>>(xp, batch, poolp, cntp, NN);
    }
    regressor_kernel<<<NB, HD>>>(poolp, cntp, depth, rg_w1, rg_b1, rg_w2, rg_b2, out);
}

// round 7
// speedup vs baseline: 1.7460x; 1.0063x over previous
#include <cuda_runtime.h>
#include <cuda_bf16.h>
#include <cstdint>
#include <cstddef>

// Problem constants (fixed-shape problem)
#define NN 100000
#define NE 600000
#define NB 512
#define HD 128
#define EDF 8

// ---------------- device scratch (256B-aligned: float4 / red.v4 paths) -------
__device__ __align__(256) float g_x0[NN];
__device__ __align__(256) float g_x[NN * HD];
__device__ __align__(256) float g_h[NN * HD];
__device__ __align__(256) float g_e[(size_t)NE * HD];     // 307 MB
__device__ __align__(256) float g_pool[NB * HD];
__device__ __align__(256) int   g_cnt[NB];

// ---------------- packed fp32x2 helpers --------------------------------------
__device__ __forceinline__ unsigned long long pack2(float x, float y) {
    unsigned long long r;
    asm("mov.b64 %0, {%1, %2};" : "=l"(r) : "f"(x), "f"(y));
    return r;
}
__device__ __forceinline__ void unpack2(unsigned long long v, float& x, float& y) {
    asm("mov.b64 {%0, %1}, %2;" : "=f"(x), "=f"(y) : "l"(v));
}
__device__ __forceinline__ void fma2(unsigned long long& c, unsigned long long a,
                                     unsigned long long b) {
    asm("fma.rn.f32x2 %0, %1, %2, %0;" : "+l"(c) : "l"(a), "l"(b));
}
__device__ __forceinline__ void red_add_v4(float* addr, float4 v) {
    asm volatile("red.global.add.v4.f32 [%0], {%1, %2, %3, %4};"
                 :: "l"(addr), "f"(v.x), "f"(v.y), "f"(v.z), "f"(v.w) : "memory");
}

// ---------------- x0 = clip(id / (2^48-1), 0, 1) -----------------------------
__global__ void x0_kernel(const int* __restrict__ ids, float* __restrict__ x0, int n) {
    int i = blockIdx.x * blockDim.x + threadIdx.x;
    if (i < n) {
        const float inv = 1.0f / 281474976710655.0f;  // 2^48 - 1
        float v = (float)ids[i] * inv;
        x0[i] = fminf(fmaxf(v, 0.0f), 1.0f);
    }
}

// ---------------- zero kernel ------------------------------------------------
__global__ void zero4_kernel(float4* __restrict__ p, int n4) {
    int i = blockIdx.x * blockDim.x + threadIdx.x;
    if (i < n4) p[i] = make_float4(0.f, 0.f, 0.f, 0.f);
}

// ---------------- inner GEMM tile: 8 rows x 8 cols per thread, LDS.128 ops ---
// cols handled by thread tc: {tc*4..tc*4+3} and {64+tc*4..64+tc*4+3}
template <int D, int LD>
__device__ __forceinline__ void gemm_tile(const float* __restrict__ sA_,
                                          const float* __restrict__ sW_,
                                          int tc, int r0,
                                          unsigned long long acc[8][4]) {
#pragma unroll 2
    for (int k0 = 0; k0 < D; k0 += 4) {
        float4 a4[8];
#pragma unroll
        for (int i = 0; i < 8; i++)
            a4[i] = *(const float4*)&sA_[(r0 + i) * LD + k0];
#pragma unroll
        for (int kk = 0; kk < 4; kk++) {
            float4 q0 = *(const float4*)&sW_[(k0 + kk) * HD + tc * 4];
            float4 q1 = *(const float4*)&sW_[(k0 + kk) * HD + 64 + tc * 4];
            unsigned long long b0 = pack2(q0.x, q0.y), b1 = pack2(q0.z, q0.w);
            unsigned long long b2 = pack2(q1.x, q1.y), b3 = pack2(q1.z, q1.w);
#pragma unroll
            for (int i = 0; i < 8; i++) {
                float a = ((const float*)&a4[i])[kk];
                unsigned long long a2 = pack2(a, a);
                fma2(acc[i][0], a2, b0);
                fma2(acc[i][1], a2, b1);
                fma2(acc[i][2], a2, b2);
                fma2(acc[i][3], a2, b3);
            }
        }
    }
}

// ---------------- fused 2-layer MLP: Y = act(relu((X[+X2])@W1+b1)@W2+b2) -----
// Tile: 128 rows x 128 cols per CTA, 256 threads, packed f32x2 FMAs.
template <int DIN, bool RELU_OUT, bool ADD2>
__global__ void __launch_bounds__(256, 1)
mlp2_kernel(const float* __restrict__ X, const float* __restrict__ X2, int M,
            const float* __restrict__ W1, const float* __restrict__ B1,
            const float* __restrict__ W2, const float* __restrict__ B2,
            float* __restrict__ Y) {
    constexpr int TM = 128;
    constexpr int LDA = (DIN == 1) ? 4 : DIN;

    extern __shared__ float sm[];
    float* sW = sm;                 // 128*128 floats (W1 then W2)
    float* sA = sW + HD * HD;       // TM * LDA
    float* sH = sA + TM * LDA;      // TM * HD

    const int tid = threadIdx.x;
    const int tr = tid >> 4;        // 0..15
    const int tc = tid & 15;        // 0..15
    const int r0 = tr * 8;
    const int m0 = blockIdx.x * TM;
    const int rows = min(TM, M - m0);

    // load W1 (vectorized)
    for (int i = tid; i < DIN * HD / 4; i += 256)
        ((float4*)sW)[i] = ((const float4*)W1)[i];
    // load X tile (zero-pad tail rows)
    if (DIN == 1) {
        for (int i = tid; i < TM; i += 256)
            sA[i * LDA] = (i < rows) ? X[m0 + i] : 0.0f;
    } else {
        constexpr int D4 = DIN / 4;
        for (int i = tid; i < TM * D4; i += 256) {
            int r = i / D4, k4 = i - r * D4;
            float4 v = make_float4(0.f, 0.f, 0.f, 0.f);
            if (r < rows) {
                v = *(const float4*)&X[(size_t)(m0 + r) * DIN + k4 * 4];
                if (ADD2) {
                    float4 w = *(const float4*)&X2[(size_t)(m0 + r) * DIN + k4 * 4];
                    v.x += w.x; v.y += w.y; v.z += w.z; v.w += w.w;
                }
            }
            *(float4*)&sA[r * LDA + k4 * 4] = v;
        }
    }
    __syncthreads();

    // ---- stage 1: sH = relu(sA @ W1 + b1) ----
    {
        unsigned long long acc[8][4];
#pragma unroll
        for (int i = 0; i < 8; i++)
#pragma unroll
            for (int m = 0; m < 4; m++) acc[i][m] = 0ull;

        if (DIN == 1) {
            float4 q0 = *(const float4*)&sW[tc * 4];
            float4 q1 = *(const float4*)&sW[64 + tc * 4];
            unsigned long long b0 = pack2(q0.x, q0.y), b1 = pack2(q0.z, q0.w);
            unsigned long long b2 = pack2(q1.x, q1.y), b3 = pack2(q1.z, q1.w);
#pragma unroll
            for (int i = 0; i < 8; i++) {
                float a = sA[(r0 + i) * LDA];
                unsigned long long a2 = pack2(a, a);
                fma2(acc[i][0], a2, b0);
                fma2(acc[i][1], a2, b1);
                fma2(acc[i][2], a2, b2);
                fma2(acc[i][3], a2, b3);
            }
        } else {
            gemm_tile<DIN, LDA>(sA, sW, tc, r0, acc);
        }

        float4 bb0 = *(const float4*)&B1[tc * 4];
        float4 bb1 = *(const float4*)&B1[64 + tc * 4];
#pragma unroll
        for (int i = 0; i < 8; i++) {
            float4 o0, o1;
            unpack2(acc[i][0], o0.x, o0.y); unpack2(acc[i][1], o0.z, o0.w);
            unpack2(acc[i][2], o1.x, o1.y); unpack2(acc[i][3], o1.z, o1.w);
            o0.x = fmaxf(o0.x + bb0.x, 0.f); o0.y = fmaxf(o0.y + bb0.y, 0.f);
            o0.z = fmaxf(o0.z + bb0.z, 0.f); o0.w = fmaxf(o0.w + bb0.w, 0.f);
            o1.x = fmaxf(o1.x + bb1.x, 0.f); o1.y = fmaxf(o1.y + bb1.y, 0.f);
            o1.z = fmaxf(o1.z + bb1.z, 0.f); o1.w = fmaxf(o1.w + bb1.w, 0.f);
            *(float4*)&sH[(r0 + i) * HD + tc * 4] = o0;
            *(float4*)&sH[(r0 + i) * HD + 64 + tc * 4] = o1;
        }
    }
    __syncthreads();
    // load W2 over W1's space
    for (int i = tid; i < HD * HD / 4; i += 256)
        ((float4*)sW)[i] = ((const float4*)W2)[i];
    __syncthreads();

    // ---- stage 2: Y = act(sH @ W2 + b2) ----
    {
        unsigned long long acc[8][4];
#pragma unroll
        for (int i = 0; i < 8; i++)
#pragma unroll
            for (int m = 0; m < 4; m++) acc[i][m] = 0ull;

        gemm_tile<HD, HD>(sH, sW, tc, r0, acc);

        float4 bb0 = *(const float4*)&B2[tc * 4];
        float4 bb1 = *(const float4*)&B2[64 + tc * 4];
#pragma unroll
        for (int i = 0; i < 8; i++) {
            if (r0 + i < rows) {
                float4 o0, o1;
                unpack2(acc[i][0], o0.x, o0.y); unpack2(acc[i][1], o0.z, o0.w);
                unpack2(acc[i][2], o1.x, o1.y); unpack2(acc[i][3], o1.z, o1.w);
                o0.x += bb0.x; o0.y += bb0.y; o0.z += bb0.z; o0.w += bb0.w;
                o1.x += bb1.x; o1.y += bb1.y; o1.z += bb1.z; o1.w += bb1.w;
                if (RELU_OUT) {
                    o0.x = fmaxf(o0.x, 0.f); o0.y = fmaxf(o0.y, 0.f);
                    o0.z = fmaxf(o0.z, 0.f); o0.w = fmaxf(o0.w, 0.f);
                    o1.x = fmaxf(o1.x, 0.f); o1.y = fmaxf(o1.y, 0.f);
                    o1.z = fmaxf(o1.z, 0.f); o1.w = fmaxf(o1.w, 0.f);
                }
                *(float4*)&Y[(size_t)(m0 + r0 + i) * HD + tc * 4] = o0;
                *(float4*)&Y[(size_t)(m0 + r0 + i) * HD + 64 + tc * 4] = o1;
            }
        }
    }
}

// ---------------- scatter: aggr[dst] += relu(x[src] + e) ---------------------
__global__ void scatter_kernel(const float* __restrict__ x, const float* __restrict__ e,
                               const int* __restrict__ src, const int* __restrict__ dst,
                               float* __restrict__ aggr, int nE) {
    long long idx = (long long)blockIdx.x * blockDim.x + threadIdx.x;
    int eidx = (int)(idx >> 5);
    if (eidx >= nE) return;
    int c4 = ((int)idx & 31) * 4;
    int s = src[eidx];
    int d = dst[eidx];
    float4 xv = *(const float4*)&x[(size_t)s * HD + c4];
    float4 ev = *(const float4*)&e[(size_t)eidx * HD + c4];
    float4 m;
    m.x = fmaxf(xv.x + ev.x, 0.0f);
    m.y = fmaxf(xv.y + ev.y, 0.0f);
    m.z = fmaxf(xv.z + ev.z, 0.0f);
    m.w = fmaxf(xv.w + ev.w, 0.0f);
    red_add_v4(&aggr[(size_t)d * HD + c4], m);
}

// ---------------- pooling ----------------------------------------------------
__global__ void zero_pool_kernel(float* __restrict__ pool, int* __restrict__ cnt) {
    int i = blockIdx.x * blockDim.x + threadIdx.x;
    if (i < NB * HD) pool[i] = 0.0f;
    if (i < NB) cnt[i] = 0;
}

__global__ void pool_kernel(const float* __restrict__ x, const int* __restrict__ batch,
                            float* __restrict__ pool, int* __restrict__ cnt, int n) {
    long long idx = (long long)blockIdx.x * blockDim.x + threadIdx.x;
    int node = (int)(idx >> 5);
    if (node >= n) return;
    int c4 = ((int)idx & 31) * 4;
    int b = batch[node];
    float4 v = *(const float4*)&x[(size_t)node * HD + c4];
    red_add_v4(&pool[(size_t)b * HD + c4], v);
    if (c4 == 0) atomicAdd(&cnt[b], 1);
}

// ---------------- regressor --------------------------------------------------
__global__ void regressor_kernel(const float* __restrict__ pool, const int* __restrict__ cnt,
                                 const float* __restrict__ depth,
                                 const float* __restrict__ w1, const float* __restrict__ b1,
                                 const float* __restrict__ w2, const float* __restrict__ b2,
                                 float* __restrict__ out) {
    int b = blockIdx.x;
    int j = threadIdx.x;  // 0..127
    __shared__ float mean[HD];
    __shared__ float red[HD];
    float c = fmaxf((float)cnt[b], 1.0f);
    mean[j] = pool[(size_t)b * HD + j] / c;
    __syncthreads();
    float acc = b1[j];
#pragma unroll 4
    for (int k = 0; k < HD; k++) acc = fmaf(mean[k], w1[k * HD + j], acc);
    acc = fmaf(depth[b], w1[HD * HD + j], acc);
    red[j] = fmaxf(acc, 0.0f) * w2[j];
    __syncthreads();
    for (int s = 64; s > 0; s >>= 1) {
        if (j < s) red[j] += red[j + s];
        __syncthreads();
    }
    if (j == 0) out[b] = red[0] + b2[0];
}

// ---------------- launch -----------------------------------------------------
extern "C" void kernel_launch(void* const* d_in, const int* in_sizes, int n_in,
                              void* d_out, int out_size) {
    const int*   node_ids  = (const int*)d_in[0];
    const int*   edge_idx  = (const int*)d_in[1];   // [2, E]
    const float* edge_attr = (const float*)d_in[2]; // [E, 8]
    const int*   batch     = (const int*)d_in[3];
    const float* depth     = (const float*)d_in[4];
    const float* id_w1 = (const float*)d_in[5];
    const float* id_b1 = (const float*)d_in[6];
    const float* id_w2 = (const float*)d_in[7];
    const float* id_b2 = (const float*)d_in[8];
    const float* ed_w1 = (const float*)d_in[9];
    const float* ed_b1 = (const float*)d_in[10];
    const float* ed_w2 = (const float*)d_in[11];
    const float* ed_b2 = (const float*)d_in[12];
    const float* c1_w1 = (const float*)d_in[13];
    const float* c1_b1 = (const float*)d_in[14];
    const float* c1_w2 = (const float*)d_in[15];
    const float* c1_b2 = (const float*)d_in[16];
    const float* c2_w1 = (const float*)d_in[17];
    const float* c2_b1 = (const float*)d_in[18];
    const float* c2_w2 = (const float*)d_in[19];
    const float* c2_b2 = (const float*)d_in[20];
    const float* rg_w1 = (const float*)d_in[21];
    const float* rg_b1 = (const float*)d_in[22];
    const float* rg_w2 = (const float*)d_in[23];
    const float* rg_b2 = (const float*)d_in[24];
    float* out = (float*)d_out;

    const int* src = edge_idx;
    const int* dst = edge_idx + NE;

    float *x0p, *xp, *hp, *ep, *poolp;
    int* cntp;
    cudaGetSymbolAddress((void**)&x0p, g_x0);
    cudaGetSymbolAddress((void**)&xp, g_x);
    cudaGetSymbolAddress((void**)&hp, g_h);
    cudaGetSymbolAddress((void**)&ep, g_e);
    cudaGetSymbolAddress((void**)&poolp, g_pool);
    cudaGetSymbolAddress((void**)&cntp, g_cnt);

    // dynamic smem: sW (128*128) + sA (128*LDA) + sH (128*128)
    const int smem1   = (HD * HD + 128 * 4   + HD * HD) * 4;
    const int smem8   = (HD * HD + 128 * 8   + HD * HD) * 4;
    const int smem128 = (HD * HD + 128 * 128 + HD * HD) * 4;
    cudaFuncSetAttribute(mlp2_kernel<1, false, false>,  cudaFuncAttributeMaxDynamicSharedMemorySize, smem1);
    cudaFuncSetAttribute(mlp2_kernel<8, false, false>,  cudaFuncAttributeMaxDynamicSharedMemorySize, smem8);
    cudaFuncSetAttribute(mlp2_kernel<128, true, true>,  cudaFuncAttributeMaxDynamicSharedMemorySize, smem128);

    const int gridN128 = (NN + 127) / 128;
    const int gridE128 = (NE + 127) / 128;
    const int nh4 = NN * HD / 4;

    // 1) id features
    x0_kernel<<<(NN + 255) / 256, 256>>>(node_ids, x0p, NN);
    zero4_kernel<<<(nh4 + 255) / 256, 256>>>((float4*)hp, nh4);
    mlp2_kernel<1, false, false><<<gridN128, 256, smem1>>>(
        x0p, nullptr, NN, id_w1, id_b1, id_w2, id_b2, xp);

    // 2) edge embeddings
    mlp2_kernel<8, false, false><<<gridE128, 256, smem8>>>(
        edge_attr, nullptr, NE, ed_w1, ed_b1, ed_w2, ed_b2, ep);

    // 3) conv 1: h = scatter(relu(x[src]+e)) ; x = relu(nn(x + h))
    {
        long long t = (long long)NE * 32;
        scatter_kernel<<<(int)((t + 255) / 256), 256>>>(xp, ep, src, dst, hp, NE);
        mlp2_kernel<128, true, true><<<gridN128, 256, smem128>>>(
            xp, hp, NN, c1_w1, c1_b1, c1_w2, c1_b2, xp);
    }
    // 4) conv 2
    {
        zero4_kernel<<<(nh4 + 255) / 256, 256>>>((float4*)hp, nh4);
        long long t = (long long)NE * 32;
        scatter_kernel<<<(int)((t + 255) / 256), 256>>>(xp, ep, src, dst, hp, NE);
        mlp2_kernel<128, true, true><<<gridN128, 256, smem128>>>(
            xp, hp, NN, c2_w1, c2_b1, c2_w2, c2_b2, xp);
    }

    // 5) pool + regressor
    zero_pool_kernel<<<(NB * HD + 255) / 256, 256>>>(poolp, cntp);
    {
        long long t = (long long)NN * 32;
        pool_kernel<<<(int)((t + 255) / 256), 256>>>(xp, batch, poolp, cntp, NN);
    }
    regressor_kernel<<<NB, HD>>>(poolp, cntp, depth, rg_w1, rg_b1, rg_w2, rg_b2, out);
}

// round 8
// speedup vs baseline: 2.0366x; 1.1664x over previous
#include <cuda_runtime.h>
#include <cuda_bf16.h>
#include <cstdint>
#include <cstddef>

// Problem constants (fixed-shape problem)
#define NN 100000
#define NE 600000
#define NB 512
#define HD 128
#define EDF 8

// ---------------- device scratch (256B-aligned: float4 / red.v4 paths) -------
__device__ __align__(256) float g_x[NN * HD];
__device__ __align__(256) float g_h[NN * HD];
__device__ __align__(256) float g_e[(size_t)NE * HD];     // 307 MB
__device__ __align__(256) float g_pool[NB * HD];
__device__ __align__(256) int   g_cnt[NB];

// ---------------- packed fp32x2 helpers --------------------------------------
__device__ __forceinline__ unsigned long long pack2(float x, float y) {
    unsigned long long r;
    asm("mov.b64 %0, {%1, %2};" : "=l"(r) : "f"(x), "f"(y));
    return r;
}
__device__ __forceinline__ void unpack2(unsigned long long v, float& x, float& y) {
    asm("mov.b64 {%0, %1}, %2;" : "=f"(x), "=f"(y) : "l"(v));
}
__device__ __forceinline__ void fma2(unsigned long long& c, unsigned long long a,
                                     unsigned long long b) {
    asm("fma.rn.f32x2 %0, %1, %2, %0;" : "+l"(c) : "l"(a), "l"(b));
}
__device__ __forceinline__ void red_add_v4(float* addr, float4 v) {
    asm volatile("red.global.add.v4.f32 [%0], {%1, %2, %3, %4};"
                 :: "l"(addr), "f"(v.x), "f"(v.y), "f"(v.z), "f"(v.w) : "memory");
}

// ---------------- zero kernel ------------------------------------------------
__global__ void zero4_kernel(float4* __restrict__ p, int n4) {
    int i = blockIdx.x * blockDim.x + threadIdx.x;
    if (i < n4) p[i] = make_float4(0.f, 0.f, 0.f, 0.f);
}

// ---------------- inner GEMM tile: 8 rows x 8 cols per thread, LDS.128 ops ---
// cols handled by thread tc: {tc*4..tc*4+3} and {64+tc*4..64+tc*4+3}
template <int D, int LD>
__device__ __forceinline__ void gemm_tile(const float* __restrict__ sA_,
                                          const float* __restrict__ sW_,
                                          int tc, int r0,
                                          unsigned long long acc[8][4]) {
#pragma unroll 2
    for (int k0 = 0; k0 < D; k0 += 4) {
        float4 a4[8];
#pragma unroll
        for (int i = 0; i < 8; i++)
            a4[i] = *(const float4*)&sA_[(r0 + i) * LD + k0];
#pragma unroll
        for (int kk = 0; kk < 4; kk++) {
            float4 q0 = *(const float4*)&sW_[(k0 + kk) * HD + tc * 4];
            float4 q1 = *(const float4*)&sW_[(k0 + kk) * HD + 64 + tc * 4];
            unsigned long long b0 = pack2(q0.x, q0.y), b1 = pack2(q0.z, q0.w);
            unsigned long long b2 = pack2(q1.x, q1.y), b3 = pack2(q1.z, q1.w);
#pragma unroll
            for (int i = 0; i < 8; i++) {
                float a = ((const float*)&a4[i])[kk];
                unsigned long long a2 = pack2(a, a);
                fma2(acc[i][0], a2, b0);
                fma2(acc[i][1], a2, b1);
                fma2(acc[i][2], a2, b2);
                fma2(acc[i][3], a2, b3);
            }
        }
    }
}

// ---------------- persistent fused 2-layer MLP -------------------------------
// Y = act(relu((X[+X2]) @ W1 + b1) @ W2 + b2)
// Weights resident in SMEM for the CTA lifetime; sA and sH alias one region.
// SMEM: [sW1: DIN*HD][sW2: HD*HD][sAH: TM*HD]
template <int DIN, bool RELU_OUT, bool ADD2, bool IDCONV>
__global__ void __launch_bounds__(256, 1)
mlp2_persist(const void* __restrict__ Xv, const float* __restrict__ X2,
             int M, int nTiles,
             const float* __restrict__ W1, const float* __restrict__ B1,
             const float* __restrict__ W2, const float* __restrict__ B2,
             float* __restrict__ Y) {
    constexpr int TM = 128;

    extern __shared__ float sm[];
    float* sW1 = sm;
    float* sW2 = sW1 + DIN * HD;
    float* sAH = sW2 + HD * HD;     // sA (TM*DIN at front) / sH (TM*HD)

    const int tid = threadIdx.x;
    const int tr = tid >> 4;        // 0..15
    const int tc = tid & 15;        // 0..15
    const int r0 = tr * 8;

    // one-time weight staging
    for (int i = tid; i < DIN * HD / 4; i += 256)
        ((float4*)sW1)[i] = ((const float4*)W1)[i];
    for (int i = tid; i < HD * HD / 4; i += 256)
        ((float4*)sW2)[i] = ((const float4*)W2)[i];
    const float4 b1a = ((const float4*)B1)[tc];
    const float4 b1b = ((const float4*)B1)[16 + tc];
    const float4 b2a = ((const float4*)B2)[tc];
    const float4 b2b = ((const float4*)B2)[16 + tc];
    __syncthreads();

    for (int t = blockIdx.x; t < nTiles; t += gridDim.x) {
        const int m0 = t * TM;
        const int rows = min(TM, M - m0);

        // ---- load sA (zero-pad tail rows) ----
        if (IDCONV) {
            const int* ids = (const int*)Xv;
            for (int i = tid; i < TM; i += 256) {
                float v = 0.0f;
                if (i < rows) {
                    const float inv = 1.0f / 281474976710655.0f;  // 2^48-1
                    v = fminf(fmaxf((float)ids[m0 + i] * inv, 0.0f), 1.0f);
                }
                sAH[i] = v;  // packed [TM] (DIN==1)
            }
        } else {
            const float* X = (const float*)Xv;
            constexpr int D4 = DIN / 4;
            for (int i = tid; i < TM * D4; i += 256) {
                int r = i / D4, k4 = i - r * D4;
                float4 v = make_float4(0.f, 0.f, 0.f, 0.f);
                if (r < rows) {
                    v = *(const float4*)&X[(size_t)(m0 + r) * DIN + k4 * 4];
                    if (ADD2) {
                        float4 w = *(const float4*)&X2[(size_t)(m0 + r) * DIN + k4 * 4];
                        v.x += w.x; v.y += w.y; v.z += w.z; v.w += w.w;
                    }
                }
                ((float4*)sAH)[i] = v;  // packed [TM][DIN]
            }
        }
        __syncthreads();

        // ---- stage 1: acc = sA @ W1 ----
        unsigned long long acc[8][4];
#pragma unroll
        for (int i = 0; i < 8; i++)
#pragma unroll
            for (int m = 0; m < 4; m++) acc[i][m] = 0ull;

        if (DIN == 1) {
            float4 q0 = *(const float4*)&sW1[tc * 4];
            float4 q1 = *(const float4*)&sW1[64 + tc * 4];
            unsigned long long b0 = pack2(q0.x, q0.y), b1 = pack2(q0.z, q0.w);
            unsigned long long b2 = pack2(q1.x, q1.y), b3 = pack2(q1.z, q1.w);
#pragma unroll
            for (int i = 0; i < 8; i++) {
                float a = sAH[r0 + i];
                unsigned long long a2 = pack2(a, a);
                fma2(acc[i][0], a2, b0);
                fma2(acc[i][1], a2, b1);
                fma2(acc[i][2], a2, b2);
                fma2(acc[i][3], a2, b3);
            }
        } else {
            gemm_tile<DIN, DIN>(sAH, sW1, tc, r0, acc);
        }
        __syncthreads();   // all stage-1 reads of sA complete before sH overwrite

        // ---- write sH = relu(acc + b1) over the sA region ----
#pragma unroll
        for (int i = 0; i < 8; i++) {
            float4 o0, o1;
            unpack2(acc[i][0], o0.x, o0.y); unpack2(acc[i][1], o0.z, o0.w);
            unpack2(acc[i][2], o1.x, o1.y); unpack2(acc[i][3], o1.z, o1.w);
            o0.x = fmaxf(o0.x + b1a.x, 0.f); o0.y = fmaxf(o0.y + b1a.y, 0.f);
            o0.z = fmaxf(o0.z + b1a.z, 0.f); o0.w = fmaxf(o0.w + b1a.w, 0.f);
            o1.x = fmaxf(o1.x + b1b.x, 0.f); o1.y = fmaxf(o1.y + b1b.y, 0.f);
            o1.z = fmaxf(o1.z + b1b.z, 0.f); o1.w = fmaxf(o1.w + b1b.w, 0.f);
            *(float4*)&sAH[(r0 + i) * HD + tc * 4] = o0;
            *(float4*)&sAH[(r0 + i) * HD + 64 + tc * 4] = o1;
        }
        __syncthreads();

        // ---- stage 2: Y = act(sH @ W2 + b2) ----
        unsigned long long acc2[8][4];
#pragma unroll
        for (int i = 0; i < 8; i++)
#pragma unroll
            for (int m = 0; m < 4; m++) acc2[i][m] = 0ull;

        gemm_tile<HD, HD>(sAH, sW2, tc, r0, acc2);

#pragma unroll
        for (int i = 0; i < 8; i++) {
            if (r0 + i < rows) {
                float4 o0, o1;
                unpack2(acc2[i][0], o0.x, o0.y); unpack2(acc2[i][1], o0.z, o0.w);
                unpack2(acc2[i][2], o1.x, o1.y); unpack2(acc2[i][3], o1.z, o1.w);
                o0.x += b2a.x; o0.y += b2a.y; o0.z += b2a.z; o0.w += b2a.w;
                o1.x += b2b.x; o1.y += b2b.y; o1.z += b2b.z; o1.w += b2b.w;
                if (RELU_OUT) {
                    o0.x = fmaxf(o0.x, 0.f); o0.y = fmaxf(o0.y, 0.f);
                    o0.z = fmaxf(o0.z, 0.f); o0.w = fmaxf(o0.w, 0.f);
                    o1.x = fmaxf(o1.x, 0.f); o1.y = fmaxf(o1.y, 0.f);
                    o1.z = fmaxf(o1.z, 0.f); o1.w = fmaxf(o1.w, 0.f);
                }
                *(float4*)&Y[(size_t)(m0 + r0 + i) * HD + tc * 4] = o0;
                *(float4*)&Y[(size_t)(m0 + r0 + i) * HD + 64 + tc * 4] = o1;
            }
        }
        __syncthreads();   // stage-2 sH reads complete before next tile's sA load
    }
}

// ---------------- scatter: aggr[dst] += relu(x[src] + e) ---------------------
__global__ void scatter_kernel(const float* __restrict__ x, const float* __restrict__ e,
                               const int* __restrict__ src, const int* __restrict__ dst,
                               float* __restrict__ aggr, int nE) {
    long long idx = (long long)blockIdx.x * blockDim.x + threadIdx.x;
    int eidx = (int)(idx >> 5);
    if (eidx >= nE) return;
    int c4 = ((int)idx & 31) * 4;
    int s = src[eidx];
    int d = dst[eidx];
    float4 xv = *(const float4*)&x[(size_t)s * HD + c4];
    float4 ev = *(const float4*)&e[(size_t)eidx * HD + c4];
    float4 m;
    m.x = fmaxf(xv.x + ev.x, 0.0f);
    m.y = fmaxf(xv.y + ev.y, 0.0f);
    m.z = fmaxf(xv.z + ev.z, 0.0f);
    m.w = fmaxf(xv.w + ev.w, 0.0f);
    red_add_v4(&aggr[(size_t)d * HD + c4], m);
}

// ---------------- pooling ----------------------------------------------------
__global__ void zero_pool_kernel(float* __restrict__ pool, int* __restrict__ cnt) {
    int i = blockIdx.x * blockDim.x + threadIdx.x;
    if (i < NB * HD) pool[i] = 0.0f;
    if (i < NB) cnt[i] = 0;
}

__global__ void pool_kernel(const float* __restrict__ x, const int* __restrict__ batch,
                            float* __restrict__ pool, int* __restrict__ cnt, int n) {
    long long idx = (long long)blockIdx.x * blockDim.x + threadIdx.x;
    int node = (int)(idx >> 5);
    if (node >= n) return;
    int c4 = ((int)idx & 31) * 4;
    int b = batch[node];
    float4 v = *(const float4*)&x[(size_t)node * HD + c4];
    red_add_v4(&pool[(size_t)b * HD + c4], v);
    if (c4 == 0) atomicAdd(&cnt[b], 1);
}

// ---------------- regressor --------------------------------------------------
__global__ void regressor_kernel(const float* __restrict__ pool, const int* __restrict__ cnt,
                                 const float* __restrict__ depth,
                                 const float* __restrict__ w1, const float* __restrict__ b1,
                                 const float* __restrict__ w2, const float* __restrict__ b2,
                                 float* __restrict__ out) {
    int b = blockIdx.x;
    int j = threadIdx.x;  // 0..127
    __shared__ float mean[HD];
    __shared__ float red[HD];
    float c = fmaxf((float)cnt[b], 1.0f);
    mean[j] = pool[(size_t)b * HD + j] / c;
    __syncthreads();
    float acc = b1[j];
#pragma unroll 4
    for (int k = 0; k < HD; k++) acc = fmaf(mean[k], w1[k * HD + j], acc);
    acc = fmaf(depth[b], w1[HD * HD + j], acc);
    red[j] = fmaxf(acc, 0.0f) * w2[j];
    __syncthreads();
    for (int s = 64; s > 0; s >>= 1) {
        if (j < s) red[j] += red[j + s];
        __syncthreads();
    }
    if (j == 0) out[b] = red[0] + b2[0];
}

// ---------------- launch -----------------------------------------------------
extern "C" void kernel_launch(void* const* d_in, const int* in_sizes, int n_in,
                              void* d_out, int out_size) {
    const int*   node_ids  = (const int*)d_in[0];
    const int*   edge_idx  = (const int*)d_in[1];   // [2, E]
    const float* edge_attr = (const float*)d_in[2]; // [E, 8]
    const int*   batch     = (const int*)d_in[3];
    const float* depth     = (const float*)d_in[4];
    const float* id_w1 = (const float*)d_in[5];
    const float* id_b1 = (const float*)d_in[6];
    const float* id_w2 = (const float*)d_in[7];
    const float* id_b2 = (const float*)d_in[8];
    const float* ed_w1 = (const float*)d_in[9];
    const float* ed_b1 = (const float*)d_in[10];
    const float* ed_w2 = (const float*)d_in[11];
    const float* ed_b2 = (const float*)d_in[12];
    const float* c1_w1 = (const float*)d_in[13];
    const float* c1_b1 = (const float*)d_in[14];
    const float* c1_w2 = (const float*)d_in[15];
    const float* c1_b2 = (const float*)d_in[16];
    const float* c2_w1 = (const float*)d_in[17];
    const float* c2_b1 = (const float*)d_in[18];
    const float* c2_w2 = (const float*)d_in[19];
    const float* c2_b2 = (const float*)d_in[20];
    const float* rg_w1 = (const float*)d_in[21];
    const float* rg_b1 = (const float*)d_in[22];
    const float* rg_w2 = (const float*)d_in[23];
    const float* rg_b2 = (const float*)d_in[24];
    float* out = (float*)d_out;

    const int* src = edge_idx;
    const int* dst = edge_idx + NE;

    float *xp, *hp, *ep, *poolp;
    int* cntp;
    cudaGetSymbolAddress((void**)&xp, g_x);
    cudaGetSymbolAddress((void**)&hp, g_h);
    cudaGetSymbolAddress((void**)&ep, g_e);
    cudaGetSymbolAddress((void**)&poolp, g_pool);
    cudaGetSymbolAddress((void**)&cntp, g_cnt);

    // dynamic smem: sW1 (DIN*HD) + sW2 (HD*HD) + sAH (128*HD)
    const int smem1   = (1 * HD   + HD * HD + 128 * HD) * 4;
    const int smem8   = (8 * HD   + HD * HD + 128 * HD) * 4;
    const int smem128 = (HD * HD  + HD * HD + 128 * HD) * 4;   // 192 KB
    cudaFuncSetAttribute(mlp2_persist<1, false, false, true>,
                         cudaFuncAttributeMaxDynamicSharedMemorySize, smem1);
    cudaFuncSetAttribute(mlp2_persist<8, false, false, false>,
                         cudaFuncAttributeMaxDynamicSharedMemorySize, smem8);
    cudaFuncSetAttribute(mlp2_persist<128, true, true, false>,
                         cudaFuncAttributeMaxDynamicSharedMemorySize, smem128);

    const int tilesN = (NN + 127) / 128;   // 782
    const int tilesE = (NE + 127) / 128;   // 4688
    const int GRID = 148;
    const int nh4 = NN * HD / 4;

    // 1) id features (x0 conversion fused into tile load)
    zero4_kernel<<<(nh4 + 255) / 256, 256>>>((float4*)hp, nh4);
    mlp2_persist<1, false, false, true><<<GRID, 256, smem1>>>(
        node_ids, nullptr, NN, tilesN, id_w1, id_b1, id_w2, id_b2, xp);

    // 2) edge embeddings
    mlp2_persist<8, false, false, false><<<GRID, 256, smem8>>>(
        edge_attr, nullptr, NE, tilesE, ed_w1, ed_b1, ed_w2, ed_b2, ep);

    // 3) conv 1: h = scatter(relu(x[src]+e)) ; x = relu(nn(x + h))
    {
        long long t = (long long)NE * 32;
        scatter_kernel<<<(int)((t + 255) / 256), 256>>>(xp, ep, src, dst, hp, NE);
        mlp2_persist<128, true, true, false><<<GRID, 256, smem128>>>(
            xp, hp, NN, tilesN, c1_w1, c1_b1, c1_w2, c1_b2, xp);
    }
    // 4) conv 2
    {
        zero4_kernel<<<(nh4 + 255) / 256, 256>>>((float4*)hp, nh4);
        long long t = (long long)NE * 32;
        scatter_kernel<<<(int)((t + 255) / 256), 256>>>(xp, ep, src, dst, hp, NE);
        mlp2_persist<128, true, true, false><<<GRID, 256, smem128>>>(
            xp, hp, NN, tilesN, c2_w1, c2_b1, c2_w2, c2_b2, xp);
    }

    // 5) pool + regressor
    zero_pool_kernel<<<(NB * HD + 255) / 256, 256>>>(poolp, cntp);
    {
        long long t = (long long)NN * 32;
        pool_kernel<<<(int)((t + 255) / 256), 256>>>(xp, batch, poolp, cntp, NN);
    }
    regressor_kernel<<<NB, HD>>>(poolp, cntp, depth, rg_w1, rg_b1, rg_w2, rg_b2, out);
}

// round 9
// speedup vs baseline: 2.0448x; 1.0040x over previous
#include <cuda_runtime.h>
#include <cuda_bf16.h>
#include <cstdint>
#include <cstddef>

// Problem constants (fixed-shape problem)
#define NN 100000
#define NE 600000
#define NB 512
#define HD 128
#define EDF 8

// ---------------- device scratch (256B-aligned: float4 / red.v4 paths) -------
__device__ __align__(256) float g_x[NN * HD];
__device__ __align__(256) float g_h[NN * HD];
__device__ __align__(256) float g_e[(size_t)NE * HD];     // 307 MB
__device__ __align__(256) float g_pool[NB * HD];
__device__ __align__(256) int   g_cnt[NB];

// ---------------- packed fp32x2 helpers --------------------------------------
__device__ __forceinline__ unsigned long long pack2(float x, float y) {
    unsigned long long r;
    asm("mov.b64 %0, {%1, %2};" : "=l"(r) : "f"(x), "f"(y));
    return r;
}
__device__ __forceinline__ void unpack2(unsigned long long v, float& x, float& y) {
    asm("mov.b64 {%0, %1}, %2;" : "=f"(x), "=f"(y) : "l"(v));
}
__device__ __forceinline__ void fma2(unsigned long long& c, unsigned long long a,
                                     unsigned long long b) {
    asm("fma.rn.f32x2 %0, %1, %2, %0;" : "+l"(c) : "l"(a), "l"(b));
}
__device__ __forceinline__ void red_add_v4(float* addr, float4 v) {
    asm volatile("red.global.add.v4.f32 [%0], {%1, %2, %3, %4};"
                 :: "l"(addr), "f"(v.x), "f"(v.y), "f"(v.z), "f"(v.w) : "memory");
}

// ---------------- zero kernel ------------------------------------------------
__global__ void zero4_kernel(float4* __restrict__ p, int n4) {
    int i = blockIdx.x * blockDim.x + threadIdx.x;
    if (i < n4) p[i] = make_float4(0.f, 0.f, 0.f, 0.f);
}

// ---------------- inner GEMM tile: 4 rows x 8 cols per thread, LDS.128 ops ---
// cols handled by thread tc: {tc*4..tc*4+3} and {64+tc*4..64+tc*4+3}
template <int D, int LD>
__device__ __forceinline__ void gemm_tile(const float* __restrict__ sA_,
                                          const float* __restrict__ sW_,
                                          int tc, int r0,
                                          unsigned long long acc[4][4]) {
#pragma unroll 2
    for (int k0 = 0; k0 < D; k0 += 4) {
        float4 a4[4];
#pragma unroll
        for (int i = 0; i < 4; i++)
            a4[i] = *(const float4*)&sA_[(r0 + i) * LD + k0];
#pragma unroll
        for (int kk = 0; kk < 4; kk++) {
            float4 q0 = *(const float4*)&sW_[(k0 + kk) * HD + tc * 4];
            float4 q1 = *(const float4*)&sW_[(k0 + kk) * HD + 64 + tc * 4];
            unsigned long long b0 = pack2(q0.x, q0.y), b1 = pack2(q0.z, q0.w);
            unsigned long long b2 = pack2(q1.x, q1.y), b3 = pack2(q1.z, q1.w);
#pragma unroll
            for (int i = 0; i < 4; i++) {
                float a = ((const float*)&a4[i])[kk];
                unsigned long long a2 = pack2(a, a);
                fma2(acc[i][0], a2, b0);
                fma2(acc[i][1], a2, b1);
                fma2(acc[i][2], a2, b2);
                fma2(acc[i][3], a2, b3);
            }
        }
    }
}

// ---------------- persistent fused 2-layer MLP (512 threads) -----------------
// Y = act(relu((X[+X2]) @ W1 + b1) @ W2 + b2)
// Weights resident in SMEM for the CTA lifetime; sA and sH alias one region.
// SMEM: [sW1: DIN*HD][sW2: HD*HD][sAH: TM*HD]
// Thread (tr=tid>>4: 0..31 -> rows tr*4..+3, tc=tid&15 -> 8 cols)
template <int DIN, bool RELU_OUT, bool ADD2, bool IDCONV>
__global__ void __launch_bounds__(512, 1)
mlp2_persist(const void* __restrict__ Xv, const float* __restrict__ X2,
             int M, int nTiles,
             const float* __restrict__ W1, const float* __restrict__ B1,
             const float* __restrict__ W2, const float* __restrict__ B2,
             float* __restrict__ Y) {
    constexpr int TM = 128;

    extern __shared__ float sm[];
    float* sW1 = sm;
    float* sW2 = sW1 + DIN * HD;
    float* sAH = sW2 + HD * HD;     // sA (TM*DIN at front) / sH (TM*HD)

    const int tid = threadIdx.x;
    const int tr = tid >> 4;        // 0..31
    const int tc = tid & 15;        // 0..15
    const int r0 = tr * 4;

    // one-time weight staging
    for (int i = tid; i < DIN * HD / 4; i += 512)
        ((float4*)sW1)[i] = ((const float4*)W1)[i];
    for (int i = tid; i < HD * HD / 4; i += 512)
        ((float4*)sW2)[i] = ((const float4*)W2)[i];
    const float4 b1a = ((const float4*)B1)[tc];
    const float4 b1b = ((const float4*)B1)[16 + tc];
    const float4 b2a = ((const float4*)B2)[tc];
    const float4 b2b = ((const float4*)B2)[16 + tc];
    __syncthreads();

    for (int t = blockIdx.x; t < nTiles; t += gridDim.x) {
        const int m0 = t * TM;
        const int rows = min(TM, M - m0);

        // ---- load sA (zero-pad tail rows) ----
        if (IDCONV) {
            const int* ids = (const int*)Xv;
            for (int i = tid; i < TM; i += 512) {
                float v = 0.0f;
                if (i < rows) {
                    const float inv = 1.0f / 281474976710655.0f;  // 2^48-1
                    v = fminf(fmaxf((float)ids[m0 + i] * inv, 0.0f), 1.0f);
                }
                sAH[i] = v;  // packed [TM] (DIN==1)
            }
        } else {
            const float* X = (const float*)Xv;
            constexpr int D4 = DIN / 4;
            for (int i = tid; i < TM * D4; i += 512) {
                int r = i / D4, k4 = i - r * D4;
                float4 v = make_float4(0.f, 0.f, 0.f, 0.f);
                if (r < rows) {
                    v = *(const float4*)&X[(size_t)(m0 + r) * DIN + k4 * 4];
                    if (ADD2) {
                        float4 w = *(const float4*)&X2[(size_t)(m0 + r) * DIN + k4 * 4];
                        v.x += w.x; v.y += w.y; v.z += w.z; v.w += w.w;
                    }
                }
                ((float4*)sAH)[i] = v;  // packed [TM][DIN]
            }
        }
        __syncthreads();

        // ---- stage 1: acc = sA @ W1 ----
        unsigned long long acc[4][4];
#pragma unroll
        for (int i = 0; i < 4; i++)
#pragma unroll
            for (int m = 0; m < 4; m++) acc[i][m] = 0ull;

        if (DIN == 1) {
            float4 q0 = *(const float4*)&sW1[tc * 4];
            float4 q1 = *(const float4*)&sW1[64 + tc * 4];
            unsigned long long b0 = pack2(q0.x, q0.y), b1 = pack2(q0.z, q0.w);
            unsigned long long b2 = pack2(q1.x, q1.y), b3 = pack2(q1.z, q1.w);
#pragma unroll
            for (int i = 0; i < 4; i++) {
                float a = sAH[r0 + i];
                unsigned long long a2 = pack2(a, a);
                fma2(acc[i][0], a2, b0);
                fma2(acc[i][1], a2, b1);
                fma2(acc[i][2], a2, b2);
                fma2(acc[i][3], a2, b3);
            }
        } else {
            gemm_tile<DIN, DIN>(sAH, sW1, tc, r0, acc);
        }
        __syncthreads();   // all stage-1 reads of sA complete before sH overwrite

        // ---- write sH = relu(acc + b1) over the sA region ----
#pragma unroll
        for (int i = 0; i < 4; i++) {
            float4 o0, o1;
            unpack2(acc[i][0], o0.x, o0.y); unpack2(acc[i][1], o0.z, o0.w);
            unpack2(acc[i][2], o1.x, o1.y); unpack2(acc[i][3], o1.z, o1.w);
            o0.x = fmaxf(o0.x + b1a.x, 0.f); o0.y = fmaxf(o0.y + b1a.y, 0.f);
            o0.z = fmaxf(o0.z + b1a.z, 0.f); o0.w = fmaxf(o0.w + b1a.w, 0.f);
            o1.x = fmaxf(o1.x + b1b.x, 0.f); o1.y = fmaxf(o1.y + b1b.y, 0.f);
            o1.z = fmaxf(o1.z + b1b.z, 0.f); o1.w = fmaxf(o1.w + b1b.w, 0.f);
            *(float4*)&sAH[(r0 + i) * HD + tc * 4] = o0;
            *(float4*)&sAH[(r0 + i) * HD + 64 + tc * 4] = o1;
        }
        __syncthreads();

        // ---- stage 2: Y = act(sH @ W2 + b2) ----
        unsigned long long acc2[4][4];
#pragma unroll
        for (int i = 0; i < 4; i++)
#pragma unroll
            for (int m = 0; m < 4; m++) acc2[i][m] = 0ull;

        gemm_tile<HD, HD>(sAH, sW2, tc, r0, acc2);

#pragma unroll
        for (int i = 0; i < 4; i++) {
            if (r0 + i < rows) {
                float4 o0, o1;
                unpack2(acc2[i][0], o0.x, o0.y); unpack2(acc2[i][1], o0.z, o0.w);
                unpack2(acc2[i][2], o1.x, o1.y); unpack2(acc2[i][3], o1.z, o1.w);
                o0.x += b2a.x; o0.y += b2a.y; o0.z += b2a.z; o0.w += b2a.w;
                o1.x += b2b.x; o1.y += b2b.y; o1.z += b2b.z; o1.w += b2b.w;
                if (RELU_OUT) {
                    o0.x = fmaxf(o0.x, 0.f); o0.y = fmaxf(o0.y, 0.f);
                    o0.z = fmaxf(o0.z, 0.f); o0.w = fmaxf(o0.w, 0.f);
                    o1.x = fmaxf(o1.x, 0.f); o1.y = fmaxf(o1.y, 0.f);
                    o1.z = fmaxf(o1.z, 0.f); o1.w = fmaxf(o1.w, 0.f);
                }
                *(float4*)&Y[(size_t)(m0 + r0 + i) * HD + tc * 4] = o0;
                *(float4*)&Y[(size_t)(m0 + r0 + i) * HD + 64 + tc * 4] = o1;
            }
        }
        __syncthreads();   // stage-2 sH reads complete before next tile's sA load
    }
}

// ---------------- scatter: aggr[dst] += relu(x[src] + e) ---------------------
__global__ void scatter_kernel(const float* __restrict__ x, const float* __restrict__ e,
                               const int* __restrict__ src, const int* __restrict__ dst,
                               float* __restrict__ aggr, int nE) {
    long long idx = (long long)blockIdx.x * blockDim.x + threadIdx.x;
    int eidx = (int)(idx >> 5);
    if (eidx >= nE) return;
    int c4 = ((int)idx & 31) * 4;
    int s = src[eidx];
    int d = dst[eidx];
    float4 xv = *(const float4*)&x[(size_t)s * HD + c4];
    float4 ev = *(const float4*)&e[(size_t)eidx * HD + c4];
    float4 m;
    m.x = fmaxf(xv.x + ev.x, 0.0f);
    m.y = fmaxf(xv.y + ev.y, 0.0f);
    m.z = fmaxf(xv.z + ev.z, 0.0f);
    m.w = fmaxf(xv.w + ev.w, 0.0f);
    red_add_v4(&aggr[(size_t)d * HD + c4], m);
}

// ---------------- pooling ----------------------------------------------------
__global__ void zero_pool_kernel(float* __restrict__ pool, int* __restrict__ cnt) {
    int i = blockIdx.x * blockDim.x + threadIdx.x;
    if (i < NB * HD) pool[i] = 0.0f;
    if (i < NB) cnt[i] = 0;
}

__global__ void pool_kernel(const float* __restrict__ x, const int* __restrict__ batch,
                            float* __restrict__ pool, int* __restrict__ cnt, int n) {
    long long idx = (long long)blockIdx.x * blockDim.x + threadIdx.x;
    int node = (int)(idx >> 5);
    if (node >= n) return;
    int c4 = ((int)idx & 31) * 4;
    int b = batch[node];
    float4 v = *(const float4*)&x[(size_t)node * HD + c4];
    red_add_v4(&pool[(size_t)b * HD + c4], v);
    if (c4 == 0) atomicAdd(&cnt[b], 1);
}

// ---------------- regressor --------------------------------------------------
__global__ void regressor_kernel(const float* __restrict__ pool, const int* __restrict__ cnt,
                                 const float* __restrict__ depth,
                                 const float* __restrict__ w1, const float* __restrict__ b1,
                                 const float* __restrict__ w2, const float* __restrict__ b2,
                                 float* __restrict__ out) {
    int b = blockIdx.x;
    int j = threadIdx.x;  // 0..127
    __shared__ float mean[HD];
    __shared__ float red[HD];
    float c = fmaxf((float)cnt[b], 1.0f);
    mean[j] = pool[(size_t)b * HD + j] / c;
    __syncthreads();
    float acc = b1[j];
#pragma unroll 4
    for (int k = 0; k < HD; k++) acc = fmaf(mean[k], w1[k * HD + j], acc);
    acc = fmaf(depth[b], w1[HD * HD + j], acc);
    red[j] = fmaxf(acc, 0.0f) * w2[j];
    __syncthreads();
    for (int s = 64; s > 0; s >>= 1) {
        if (j < s) red[j] += red[j + s];
        __syncthreads();
    }
    if (j == 0) out[b] = red[0] + b2[0];
}

// ---------------- launch -----------------------------------------------------
extern "C" void kernel_launch(void* const* d_in, const int* in_sizes, int n_in,
                              void* d_out, int out_size) {
    const int*   node_ids  = (const int*)d_in[0];
    const int*   edge_idx  = (const int*)d_in[1];   // [2, E]
    const float* edge_attr = (const float*)d_in[2]; // [E, 8]
    const int*   batch     = (const int*)d_in[3];
    const float* depth     = (const float*)d_in[4];
    const float* id_w1 = (const float*)d_in[5];
    const float* id_b1 = (const float*)d_in[6];
    const float* id_w2 = (const float*)d_in[7];
    const float* id_b2 = (const float*)d_in[8];
    const float* ed_w1 = (const float*)d_in[9];
    const float* ed_b1 = (const float*)d_in[10];
    const float* ed_w2 = (const float*)d_in[11];
    const float* ed_b2 = (const float*)d_in[12];
    const float* c1_w1 = (const float*)d_in[13];
    const float* c1_b1 = (const float*)d_in[14];
    const float* c1_w2 = (const float*)d_in[15];
    const float* c1_b2 = (const float*)d_in[16];
    const float* c2_w1 = (const float*)d_in[17];
    const float* c2_b1 = (const float*)d_in[18];
    const float* c2_w2 = (const float*)d_in[19];
    const float* c2_b2 = (const float*)d_in[20];
    const float* rg_w1 = (const float*)d_in[21];
    const float* rg_b1 = (const float*)d_in[22];
    const float* rg_w2 = (const float*)d_in[23];
    const float* rg_b2 = (const float*)d_in[24];
    float* out = (float*)d_out;

    const int* src = edge_idx;
    const int* dst = edge_idx + NE;

    float *xp, *hp, *ep, *poolp;
    int* cntp;
    cudaGetSymbolAddress((void**)&xp, g_x);
    cudaGetSymbolAddress((void**)&hp, g_h);
    cudaGetSymbolAddress((void**)&ep, g_e);
    cudaGetSymbolAddress((void**)&poolp, g_pool);
    cudaGetSymbolAddress((void**)&cntp, g_cnt);

    // dynamic smem: sW1 (DIN*HD) + sW2 (HD*HD) + sAH (128*HD)
    const int smem1   = (1 * HD   + HD * HD + 128 * HD) * 4;
    const int smem8   = (8 * HD   + HD * HD + 128 * HD) * 4;
    const int smem128 = (HD * HD  + HD * HD + 128 * HD) * 4;   // 192 KB
    cudaFuncSetAttribute(mlp2_persist<1, false, false, true>,
                         cudaFuncAttributeMaxDynamicSharedMemorySize, smem1);
    cudaFuncSetAttribute(mlp2_persist<8, false, false, false>,
                         cudaFuncAttributeMaxDynamicSharedMemorySize, smem8);
    cudaFuncSetAttribute(mlp2_persist<128, true, true, false>,
                         cudaFuncAttributeMaxDynamicSharedMemorySize, smem128);

    const int tilesN = (NN + 127) / 128;   // 782
    const int tilesE = (NE + 127) / 128;   // 4688
    const int GRID = 148;
    const int nh4 = NN * HD / 4;

    // 1) id features (x0 conversion fused into tile load)
    zero4_kernel<<<(nh4 + 255) / 256, 256>>>((float4*)hp, nh4);
    mlp2_persist<1, false, false, true><<<GRID, 512, smem1>>>(
        node_ids, nullptr, NN, tilesN, id_w1, id_b1, id_w2, id_b2, xp);

    // 2) edge embeddings
    mlp2_persist<8, false, false, false><<<GRID, 512, smem8>>>(
        edge_attr, nullptr, NE, tilesE, ed_w1, ed_b1, ed_w2, ed_b2, ep);

    // 3) conv 1: h = scatter(relu(x[src]+e)) ; x = relu(nn(x + h))
    {
        long long t = (long long)NE * 32;
        scatter_kernel<<<(int)((t + 255) / 256), 256>>>(xp, ep, src, dst, hp, NE);
        mlp2_persist<128, true, true, false><<<GRID, 512, smem128>>>(
            xp, hp, NN, tilesN, c1_w1, c1_b1, c1_w2, c1_b2, xp);
    }
    // 4) conv 2
    {
        zero4_kernel<<<(nh4 + 255) / 256, 256>>>((float4*)hp, nh4);
        long long t = (long long)NE * 32;
        scatter_kernel<<<(int)((t + 255) / 256), 256>>>(xp, ep, src, dst, hp, NE);
        mlp2_persist<128, true, true, false><<<GRID, 512, smem128>>>(
            xp, hp, NN, tilesN, c2_w1, c2_b1, c2_w2, c2_b2, xp);
    }

    // 5) pool + regressor
    zero_pool_kernel<<<(NB * HD + 255) / 256, 256>>>(poolp, cntp);
    {
        long long t = (long long)NN * 32;
        pool_kernel<<<(int)((t + 255) / 256), 256>>>(xp, batch, poolp, cntp, NN);
    }
    regressor_kernel<<<NB, HD>>>(poolp, cntp, depth, rg_w1, rg_b1, rg_w2, rg_b2, out);
}